// round 12
// baseline (speedup 1.0000x reference)
#include <cuda_runtime.h>
#include <cuda_fp16.h>
#include <cstdint>

#define BATCH 4
#define SEQ   4096
#define DMODEL 1024
#define DIM   128
#define NE    384
#define MTOT  (BATCH * SEQ)   // 16384

// Device-global scratch (no cudaMalloc allowed)
__device__ __half g_Qh[MTOT * DIM];                  // pre-scaled, perm16 dim-interleaved
__device__ __half g_Kh[MTOT * DIM];                  // plain [t][d]
__device__ __half g_Vth[(size_t)BATCH * DIM * SEQ];  // plain transposed [b][d][t]
__device__ __half g_Xh[(size_t)MTOT * DMODEL];       // x in fp16, plain [row][k]
__device__ __half g_Wh[(size_t)NE * DMODEL];         // W in fp16, transposed [n][k]

// ---------------------------------------------------------------------------
// helpers
// ---------------------------------------------------------------------------
__device__ __forceinline__ int perm16(int j) {
    int p = (j >> 1) & 7;
    int pos = ((p & 3) << 1) | ((p >> 2) & 1);
    return (j & ~15) | (pos << 1) | (j & 1);
}

__device__ __forceinline__ void mma_f16(float* d, const uint32_t* a, uint32_t b0, uint32_t b1) {
    asm volatile(
        "mma.sync.aligned.m16n8k16.row.col.f32.f16.f16.f32 "
        "{%0,%1,%2,%3}, {%4,%5,%6,%7}, {%8,%9}, {%0,%1,%2,%3};"
        : "+f"(d[0]), "+f"(d[1]), "+f"(d[2]), "+f"(d[3])
        : "r"(a[0]), "r"(a[1]), "r"(a[2]), "r"(a[3]), "r"(b0), "r"(b1));
}

#define LDSM4(r0, r1, r2, r3, addr) \
    asm volatile("ldmatrix.sync.aligned.m8n8.x4.shared.b16 {%0,%1,%2,%3}, [%4];" \
                 : "=r"(r0), "=r"(r1), "=r"(r2), "=r"(r3) : "r"(addr))

__device__ __forceinline__ void cp16(void* smem, const void* gmem) {
    uint32_t s = (uint32_t)__cvta_generic_to_shared(smem);
    asm volatile("cp.async.cg.shared.global [%0], [%1], 16;" :: "r"(s), "l"(gmem));
}
__device__ __forceinline__ void cp_commit() {
    asm volatile("cp.async.commit_group;");
}
__device__ __forceinline__ void cp_wait_all() {
    asm volatile("cp.async.wait_group 0;");
}

// deg-3 economized exp2, FMA pipe only.
__device__ __forceinline__ float fast_exp2(float x) {
    x = fmaxf(x, -126.0f);
    float r = x + 12582912.0f;
    float f = x - (r - 12582912.0f);
    float p = 0.05550411f;
    p = fmaf(p, f, 0.24263110f);
    p = fmaf(p, f, 0.69314718f);
    p = fmaf(p, f, 0.99992485f);
    float s = __int_as_float((__float_as_int(r) - 0x4B400000 + 127) << 23);
    return p * s;
}

__device__ __forceinline__ uint32_t pack_h2(float a, float b) {
    __half2 h = __floats2half2_rn(a, b);
    return *reinterpret_cast<uint32_t*>(&h);
}

// ---------------------------------------------------------------------------
// Convert kernels
// ---------------------------------------------------------------------------
__global__ __launch_bounds__(256)
void conv_x_kernel(const float* __restrict__ x) {
    size_t i = (size_t)blockIdx.x * 256 + threadIdx.x;  // one float4
    float4 v = ((const float4*)x)[i];
    uint2 o;
    o.x = pack_h2(v.x, v.y);
    o.y = pack_h2(v.z, v.w);
    ((uint2*)g_Xh)[i] = o;
}

__global__ __launch_bounds__(256)
void conv_w_kernel(const float* __restrict__ W) {
    int idx = blockIdx.x * 256 + threadIdx.x;   // over NE*DMODEL
    int n = idx / DMODEL, k = idx - n * DMODEL;
    g_Wh[idx] = __float2half_rn(W[(size_t)k * NE + n]);
}

// ---------------------------------------------------------------------------
// Kernel 1: QKV projection (unchanged from round 9/11)
// ---------------------------------------------------------------------------
#define QASTR 40

__global__ __launch_bounds__(256)
void qkv_mma_kernel(const float* __restrict__ bias) {
    __shared__ __half Ax[2][128 * QASTR];
    __shared__ __half Bx[2][128 * QASTR];

    const int row0 = blockIdx.x * 128;
    const int col0 = blockIdx.y * 128;
    const int tid = threadIdx.x;
    const int w = tid >> 5, lane = tid & 31;
    const int g = lane >> 2, c = lane & 3;
    const int wm = w >> 1, wn = w & 1;

    float acc[2][8][4];
#pragma unroll
    for (int mt = 0; mt < 2; mt++)
#pragma unroll
        for (int nt = 0; nt < 8; nt++)
#pragma unroll
            for (int j = 0; j < 4; j++) acc[mt][nt][j] = 0.0f;

#pragma unroll
    for (int it2 = 0; it2 < 2; it2++) {
        int slot = tid + it2 * 256;
        int r = slot >> 2, sg = (slot & 3) * 8;
        cp16(&Ax[0][r * QASTR + sg], g_Xh + (size_t)(row0 + r) * DMODEL + sg);
        cp16(&Bx[0][r * QASTR + sg], g_Wh + (size_t)(col0 + r) * DMODEL + sg);
    }
    cp_commit();

    for (int t = 0; t < 32; t++) {
        cp_wait_all();
        __syncthreads();
        if (t < 31) {
            int k0 = (t + 1) * 32;
            int bo = (t + 1) & 1;
#pragma unroll
            for (int it2 = 0; it2 < 2; it2++) {
                int slot = tid + it2 * 256;
                int r = slot >> 2, sg = (slot & 3) * 8;
                cp16(&Ax[bo][r * QASTR + sg], g_Xh + (size_t)(row0 + r) * DMODEL + k0 + sg);
                cp16(&Bx[bo][r * QASTR + sg], g_Wh + (size_t)(col0 + r) * DMODEL + k0 + sg);
            }
            cp_commit();
        }

        const __half* pA = Ax[t & 1];
        const __half* pB = Bx[t & 1];

#pragma unroll
        for (int ks = 0; ks < 2; ks++) {
            uint32_t ah[2][4];
#pragma unroll
            for (int mt = 0; mt < 2; mt++) {
                int ar = wm * 32 + mt * 16 + g;
                const __half* p = pA + ar * QASTR + ks * 16 + 2 * c;
                ah[mt][0] = *(const uint32_t*)p;
                ah[mt][1] = *(const uint32_t*)(p + 8 * QASTR);
                ah[mt][2] = *(const uint32_t*)(p + 8);
                ah[mt][3] = *(const uint32_t*)(p + 8 * QASTR + 8);
            }
#pragma unroll
            for (int nt = 0; nt < 8; nt++) {
                int bc = wn * 64 + nt * 8 + g;
                const __half* pb = pB + bc * QASTR + ks * 16 + 2 * c;
                uint32_t bh0 = *(const uint32_t*)pb;
                uint32_t bh1 = *(const uint32_t*)(pb + 8);
#pragma unroll
                for (int mt = 0; mt < 2; mt++)
                    mma_f16(acc[mt][nt], ah[mt], bh0, bh1);
            }
        }
    }

    const float pre = 0.12751745f;  // 128^-0.5 * log2(e)
#pragma unroll
    for (int mt = 0; mt < 2; mt++) {
#pragma unroll
        for (int nt = 0; nt < 8; nt++) {
            int er = row0 + wm * 32 + mt * 16 + g;
            int ec = col0 + wn * 64 + nt * 8 + 2 * c;
#pragma unroll
            for (int j = 0; j < 4; j++) {
                int r = er + ((j >= 2) ? 8 : 0);
                int e = ec + (j & 1);
                float v = acc[mt][nt][j] + bias[e];
                int d = e / 3, wh = e - 3 * d;
                if (wh == 0) {
                    g_Qh[(size_t)r * DIM + perm16(d)] = __float2half_rn(v * pre);
                } else if (wh == 1) {
                    g_Kh[(size_t)r * DIM + d] = __float2half_rn(v);
                } else {
                    int b = r >> 12, tt = r & (SEQ - 1);
                    g_Vth[((size_t)b * DIM + d) * SEQ + tt] = __float2half_rn(v);
                }
            }
        }
    }
}

// ---------------------------------------------------------------------------
// Kernel 2: flash attention, split-warp form for 2 CTAs/SM.
// q-tile 64, 8 warps = 4 row-groups x 2 halves; S splits keys, PV splits dims.
// Fixed-shift softmax p = 2^(s-8); P via smem; l combined across halves.
// ---------------------------------------------------------------------------
#define KSTR 136
#define VSTR 72
#define PSTR 72
#define TK   64
#define NT64 (SEQ / TK)
#define SHIFT 8.0f
#define KSTAGE (64 * KSTR)
#define VSTAGE (128 * VSTR)
#define ATTN_SMEM ((2 * KSTAGE + 2 * VSTAGE + 64 * PSTR) * 2)  // 80640 B

__global__ __launch_bounds__(256, 2)
void attn_kernel(float* __restrict__ out) {
    extern __shared__ char asm_[];
    __half* Ksb = (__half*)asm_;                 // [2][KSTAGE]
    __half* Vtb = Ksb + 2 * KSTAGE;              // [2][VSTAGE]
    __half* Ps  = Vtb + 2 * VSTAGE;              // [64][PSTR]
    __shared__ float Lbuf[2][64];

    const int b  = blockIdx.y;
    const int q0 = blockIdx.x * 64;
    const int tid = threadIdx.x;
    const int w = tid >> 5, lane = tid & 31;
    const int g = lane >> 2, c = lane & 3;
    const int rg = w & 3;        // row group
    const int kh = w >> 2;       // key half (S) == dim half (PV)

    const __half* Qg = g_Qh + (size_t)b * SEQ * DIM;
    const __half* Kg = g_Kh + (size_t)b * SEQ * DIM;
    const __half* Vg = g_Vth + (size_t)b * DIM * SEQ;

    const uint32_t ksm = (uint32_t)__cvta_generic_to_shared(Ksb);
    const uint32_t vsm = (uint32_t)__cvta_generic_to_shared(Vtb);
    const uint32_t psm = (uint32_t)__cvta_generic_to_shared(Ps);

    const uint32_t klane = (uint32_t)(((lane & 7) * KSTR + (lane >> 3) * 8) * 2);
    const uint32_t vlane = (uint32_t)(((lane & 7) * VSTR + (lane >> 3) * 8) * 2);
    const uint32_t palane = (uint32_t)(((rg * 16 + ((lane >> 3) & 1) * 8 + (lane & 7)) * PSTR
                                        + (lane >> 4) * 8) * 2);

    uint32_t qf[8][4];
    {
        size_t qr = (size_t)(q0 + rg * 16 + g) * DIM;
#pragma unroll
        for (int ks = 0; ks < 8; ks++) {
            uint2 t0 = *(const uint2*)(Qg + qr + ks * 16 + 4 * c);
            uint2 t1 = *(const uint2*)(Qg + qr + 8 * DIM + ks * 16 + 4 * c);
            qf[ks][0] = t0.x; qf[ks][2] = t0.y;
            qf[ks][1] = t1.x; qf[ks][3] = t1.y;
        }
    }

    float o[8][4];
#pragma unroll
    for (int nt = 0; nt < 8; nt++)
#pragma unroll
        for (int j = 0; j < 4; j++) o[nt][j] = 0.0f;
    float l0 = 0.0f, l1 = 0.0f;

#pragma unroll
    for (int i = 0; i < 4; i++) {
        int slot = tid + i * 256;
        int r = slot >> 4, cc = (slot & 15) * 8;
        cp16(Ksb + r * KSTR + cc, Kg + (size_t)r * DIM + cc);
    }
#pragma unroll
    for (int i = 0; i < 4; i++) {
        int slot = tid + i * 256;
        int r = slot >> 3, cc = (slot & 7) * 8;
        cp16(Vtb + r * VSTR + cc, Vg + (size_t)r * SEQ + cc);
    }
    cp_commit();

    for (int t = 0; t < NT64; t++) {
        cp_wait_all();
        __syncthreads();   // K/V ready; previous tile's P reads done
        if (t < NT64 - 1) {
            int k0 = (t + 1) * TK;
            int kso = ((t + 1) & 1) * KSTAGE;
            int vso = ((t + 1) & 1) * VSTAGE;
#pragma unroll
            for (int i = 0; i < 4; i++) {
                int slot = tid + i * 256;
                int r = slot >> 4, cc = (slot & 15) * 8;
                cp16(Ksb + kso + r * KSTR + cc, Kg + (size_t)(k0 + r) * DIM + cc);
            }
#pragma unroll
            for (int i = 0; i < 4; i++) {
                int slot = tid + i * 256;
                int r = slot >> 3, cc = (slot & 7) * 8;
                cp16(Vtb + vso + r * VSTR + cc, Vg + (size_t)r * SEQ + k0 + cc);
            }
            cp_commit();
        }

        // ---- S phase: rows rg*16.., keys kh*32 + nt*8 ----
        const uint32_t kbase = ksm + (uint32_t)((t & 1) * KSTAGE * 2)
                             + (uint32_t)(kh * 32 * KSTR * 2) + klane;
        float s[4][4];
#pragma unroll
        for (int nt = 0; nt < 4; nt++) {
            s[nt][0] = 0.0f; s[nt][1] = 0.0f; s[nt][2] = 0.0f; s[nt][3] = 0.0f;
        }
#pragma unroll
        for (int q = 0; q < 4; q++) {
#pragma unroll
            for (int nt = 0; nt < 4; nt++) {
                uint32_t b0, b1, b2, b3;
                LDSM4(b0, b1, b2, b3, kbase + (uint32_t)(nt * 8 * KSTR * 2) + q * 64);
                mma_f16(s[nt], qf[2 * q],     b0, b1);
                mma_f16(s[nt], qf[2 * q + 1], b2, b3);
            }
        }

        // ---- softmax: p = 2^(s-8), write P (fp16) to smem ----
#pragma unroll
        for (int nt = 0; nt < 4; nt++) {
            float e0 = fast_exp2(s[nt][0] - SHIFT);
            float e1 = fast_exp2(s[nt][1] - SHIFT);
            float e2 = fast_exp2(s[nt][2] - SHIFT);
            float e3 = fast_exp2(s[nt][3] - SHIFT);
            l0 += e0 + e1;
            l1 += e2 + e3;
            int col = kh * 32 + nt * 8 + 2 * c;
            uint32_t lo = pack_h2(e0, e1);
            uint32_t hi = pack_h2(e2, e3);
            *(uint32_t*)(Ps + (rg * 16 + g) * PSTR + col) = lo;
            *(uint32_t*)(Ps + (rg * 16 + g + 8) * PSTR + col) = hi;
        }
        __syncthreads();   // P complete for all warps

        // ---- PV phase: rows rg*16.., dims kh*64 + nt*8 ----
        const uint32_t vbase = vsm + (uint32_t)((t & 1) * VSTAGE * 2)
                             + (uint32_t)(kh * 64 * VSTR * 2) + vlane;
#pragma unroll
        for (int q2 = 0; q2 < 2; q2++) {
            uint32_t af0[4], af1[4];
            LDSM4(af0[0], af0[1], af0[2], af0[3], psm + palane + (uint32_t)(q2 * 64));
            LDSM4(af1[0], af1[1], af1[2], af1[3], psm + palane + (uint32_t)(q2 * 64 + 32));
#pragma unroll
            for (int nt = 0; nt < 8; nt++) {
                uint32_t b0, b1, b2, b3;
                LDSM4(b0, b1, b2, b3, vbase + (uint32_t)(nt * 8 * VSTR * 2) + q2 * 64);
                mma_f16(o[nt], af0, b0, b1);
                mma_f16(o[nt], af1, b2, b3);
            }
        }
    }

    // ---- l: reduce over c lanes, combine key halves via smem ----
    l0 += __shfl_xor_sync(0xffffffffu, l0, 1);
    l0 += __shfl_xor_sync(0xffffffffu, l0, 2);
    l1 += __shfl_xor_sync(0xffffffffu, l1, 1);
    l1 += __shfl_xor_sync(0xffffffffu, l1, 2);
    if (c == 0) {
        Lbuf[kh][rg * 16 + g] = l0;
        Lbuf[kh][rg * 16 + g + 8] = l1;
    }
    __syncthreads();
    float inv0 = 1.0f / (Lbuf[0][rg * 16 + g] + Lbuf[1][rg * 16 + g]);
    float inv1 = 1.0f / (Lbuf[0][rg * 16 + g + 8] + Lbuf[1][rg * 16 + g + 8]);

    size_t r0 = ((size_t)b * SEQ + q0 + rg * 16 + g) * DIM + kh * 64;
    size_t r1 = r0 + 8 * DIM;
#pragma unroll
    for (int nt = 0; nt < 8; nt++) {
        int col = nt * 8 + 2 * c;
        *(float2*)&out[r0 + col] = make_float2(o[nt][0] * inv0, o[nt][1] * inv0);
        *(float2*)&out[r1 + col] = make_float2(o[nt][2] * inv1, o[nt][3] * inv1);
    }
}

// ---------------------------------------------------------------------------
extern "C" void kernel_launch(void* const* d_in, const int* in_sizes, int n_in,
                              void* d_out, int out_size) {
    const float* x    = (const float*)d_in[0];
    const float* W    = (const float*)d_in[1];
    const float* bias = (const float*)d_in[2];
    float* out = (float*)d_out;

    conv_x_kernel<<<(MTOT * DMODEL / 4) / 256, 256>>>(x);
    conv_w_kernel<<<(NE * DMODEL) / 256, 256>>>(W);

    dim3 g1(128, 3);
    qkv_mma_kernel<<<g1, 256>>>(bias);

    cudaFuncSetAttribute(attn_kernel, cudaFuncAttributeMaxDynamicSharedMemorySize,
                         ATTN_SMEM);
    dim3 g2(SEQ / 64, BATCH);
    attn_kernel<<<g2, 256, ATTN_SMEM>>>(out);
}

// round 13
// speedup vs baseline: 1.0488x; 1.0488x over previous
#include <cuda_runtime.h>
#include <cuda_fp16.h>
#include <cstdint>

#define BATCH 4
#define SEQ   4096
#define DMODEL 1024
#define DIM   128
#define NE    384
#define MTOT  (BATCH * SEQ)   // 16384

// Device-global scratch (no cudaMalloc allowed)
__device__ __half g_Qh[MTOT * DIM];                  // pre-scaled, perm16 dim-interleaved
__device__ __half g_Kh[MTOT * DIM];                  // plain [t][d]
__device__ __half g_Vth[(size_t)BATCH * DIM * SEQ];  // plain transposed [b][d][t]
__device__ __half g_Xh[(size_t)MTOT * DMODEL];       // x in fp16, plain [row][k]
__device__ __half g_Wh[(size_t)NE * DMODEL];         // W in fp16, transposed [n][k]

// ---------------------------------------------------------------------------
// helpers
// ---------------------------------------------------------------------------
__device__ __forceinline__ int perm16(int j) {
    int p = (j >> 1) & 7;
    int pos = ((p & 3) << 1) | ((p >> 2) & 1);
    return (j & ~15) | (pos << 1) | (j & 1);
}

__device__ __forceinline__ void mma_f16(float* d, const uint32_t* a, uint32_t b0, uint32_t b1) {
    asm volatile(
        "mma.sync.aligned.m16n8k16.row.col.f32.f16.f16.f32 "
        "{%0,%1,%2,%3}, {%4,%5,%6,%7}, {%8,%9}, {%0,%1,%2,%3};"
        : "+f"(d[0]), "+f"(d[1]), "+f"(d[2]), "+f"(d[3])
        : "r"(a[0]), "r"(a[1]), "r"(a[2]), "r"(a[3]), "r"(b0), "r"(b1));
}

#define LDSM4(r0, r1, r2, r3, addr) \
    asm volatile("ldmatrix.sync.aligned.m8n8.x4.shared.b16 {%0,%1,%2,%3}, [%4];" \
                 : "=r"(r0), "=r"(r1), "=r"(r2), "=r"(r3) : "r"(addr))

__device__ __forceinline__ void cp16(void* smem, const void* gmem) {
    uint32_t s = (uint32_t)__cvta_generic_to_shared(smem);
    asm volatile("cp.async.cg.shared.global [%0], [%1], 16;" :: "r"(s), "l"(gmem));
}
__device__ __forceinline__ void cp_commit() {
    asm volatile("cp.async.commit_group;");
}
__device__ __forceinline__ void cp_wait_all() {
    asm volatile("cp.async.wait_group 0;");
}

// deg-3 economized exp2, FMA pipe only.
__device__ __forceinline__ float fast_exp2(float x) {
    x = fmaxf(x, -126.0f);
    float r = x + 12582912.0f;
    float f = x - (r - 12582912.0f);
    float p = 0.05550411f;
    p = fmaf(p, f, 0.24263110f);
    p = fmaf(p, f, 0.69314718f);
    p = fmaf(p, f, 0.99992485f);
    float s = __int_as_float((__float_as_int(r) - 0x4B400000 + 127) << 23);
    return p * s;
}

__device__ __forceinline__ uint32_t pack_h2(float a, float b) {
    __half2 h = __floats2half2_rn(a, b);
    return *reinterpret_cast<uint32_t*>(&h);
}

// ---------------------------------------------------------------------------
// Convert kernels
// ---------------------------------------------------------------------------
__global__ __launch_bounds__(256)
void conv_x_kernel(const float* __restrict__ x) {
    size_t i = (size_t)blockIdx.x * 256 + threadIdx.x;  // one float4
    float4 v = ((const float4*)x)[i];
    uint2 o;
    o.x = pack_h2(v.x, v.y);
    o.y = pack_h2(v.z, v.w);
    ((uint2*)g_Xh)[i] = o;
}

__global__ __launch_bounds__(256)
void conv_w_kernel(const float* __restrict__ W) {
    int idx = blockIdx.x * 256 + threadIdx.x;   // over NE*DMODEL
    int n = idx / DMODEL, k = idx - n * DMODEL;
    g_Wh[idx] = __float2half_rn(W[(size_t)k * NE + n]);
}

// ---------------------------------------------------------------------------
// Kernel 1: QKV projection (unchanged from round 9/11)
// ---------------------------------------------------------------------------
#define QASTR 40

__global__ __launch_bounds__(256)
void qkv_mma_kernel(const float* __restrict__ bias) {
    __shared__ __half Ax[2][128 * QASTR];
    __shared__ __half Bx[2][128 * QASTR];

    const int row0 = blockIdx.x * 128;
    const int col0 = blockIdx.y * 128;
    const int tid = threadIdx.x;
    const int w = tid >> 5, lane = tid & 31;
    const int g = lane >> 2, c = lane & 3;
    const int wm = w >> 1, wn = w & 1;

    float acc[2][8][4];
#pragma unroll
    for (int mt = 0; mt < 2; mt++)
#pragma unroll
        for (int nt = 0; nt < 8; nt++)
#pragma unroll
            for (int j = 0; j < 4; j++) acc[mt][nt][j] = 0.0f;

#pragma unroll
    for (int it2 = 0; it2 < 2; it2++) {
        int slot = tid + it2 * 256;
        int r = slot >> 2, sg = (slot & 3) * 8;
        cp16(&Ax[0][r * QASTR + sg], g_Xh + (size_t)(row0 + r) * DMODEL + sg);
        cp16(&Bx[0][r * QASTR + sg], g_Wh + (size_t)(col0 + r) * DMODEL + sg);
    }
    cp_commit();

    for (int t = 0; t < 32; t++) {
        cp_wait_all();
        __syncthreads();
        if (t < 31) {
            int k0 = (t + 1) * 32;
            int bo = (t + 1) & 1;
#pragma unroll
            for (int it2 = 0; it2 < 2; it2++) {
                int slot = tid + it2 * 256;
                int r = slot >> 2, sg = (slot & 3) * 8;
                cp16(&Ax[bo][r * QASTR + sg], g_Xh + (size_t)(row0 + r) * DMODEL + k0 + sg);
                cp16(&Bx[bo][r * QASTR + sg], g_Wh + (size_t)(col0 + r) * DMODEL + k0 + sg);
            }
            cp_commit();
        }

        const __half* pA = Ax[t & 1];
        const __half* pB = Bx[t & 1];

#pragma unroll
        for (int ks = 0; ks < 2; ks++) {
            uint32_t ah[2][4];
#pragma unroll
            for (int mt = 0; mt < 2; mt++) {
                int ar = wm * 32 + mt * 16 + g;
                const __half* p = pA + ar * QASTR + ks * 16 + 2 * c;
                ah[mt][0] = *(const uint32_t*)p;
                ah[mt][1] = *(const uint32_t*)(p + 8 * QASTR);
                ah[mt][2] = *(const uint32_t*)(p + 8);
                ah[mt][3] = *(const uint32_t*)(p + 8 * QASTR + 8);
            }
#pragma unroll
            for (int nt = 0; nt < 8; nt++) {
                int bc = wn * 64 + nt * 8 + g;
                const __half* pb = pB + bc * QASTR + ks * 16 + 2 * c;
                uint32_t bh0 = *(const uint32_t*)pb;
                uint32_t bh1 = *(const uint32_t*)(pb + 8);
#pragma unroll
                for (int mt = 0; mt < 2; mt++)
                    mma_f16(acc[mt][nt], ah[mt], bh0, bh1);
            }
        }
    }

    const float pre = 0.12751745f;  // 128^-0.5 * log2(e)
#pragma unroll
    for (int mt = 0; mt < 2; mt++) {
#pragma unroll
        for (int nt = 0; nt < 8; nt++) {
            int er = row0 + wm * 32 + mt * 16 + g;
            int ec = col0 + wn * 64 + nt * 8 + 2 * c;
#pragma unroll
            for (int j = 0; j < 4; j++) {
                int r = er + ((j >= 2) ? 8 : 0);
                int e = ec + (j & 1);
                float v = acc[mt][nt][j] + bias[e];
                int d = e / 3, wh = e - 3 * d;
                if (wh == 0) {
                    g_Qh[(size_t)r * DIM + perm16(d)] = __float2half_rn(v * pre);
                } else if (wh == 1) {
                    g_Kh[(size_t)r * DIM + d] = __float2half_rn(v);
                } else {
                    int b = r >> 12, tt = r & (SEQ - 1);
                    g_Vth[((size_t)b * DIM + d) * SEQ + tt] = __float2half_rn(v);
                }
            }
        }
    }
}

// ---------------------------------------------------------------------------
// Kernel 2: flash attention, split-warp, 512 threads, q-tile 128.
// 16 warps = 8 row-groups x 2 halves; S splits keys, PV splits dims.
// Same AI as round 11 (128 q per 64-key tile) at 4 warps/SMSP.
// Fixed-shift softmax p = 2^(s-8); P via smem; l combined across halves.
// ---------------------------------------------------------------------------
#define KSTR 136
#define VSTR 72
#define PSTR 72
#define TK   64
#define NT64 (SEQ / TK)
#define SHIFT 8.0f
#define KSTAGE (64 * KSTR)
#define VSTAGE (128 * VSTR)
#define ATTN_SMEM ((2 * KSTAGE + 2 * VSTAGE + 128 * PSTR) * 2)  // 89856 B

__global__ __launch_bounds__(512, 1)
void attn_kernel(float* __restrict__ out) {
    extern __shared__ char asm_[];
    __half* Ksb = (__half*)asm_;                 // [2][KSTAGE]
    __half* Vtb = Ksb + 2 * KSTAGE;              // [2][VSTAGE]
    __half* Ps  = Vtb + 2 * VSTAGE;              // [128][PSTR]
    __shared__ float Lbuf[2][128];

    const int b  = blockIdx.y;
    const int q0 = blockIdx.x * 128;
    const int tid = threadIdx.x;
    const int w = tid >> 5, lane = tid & 31;
    const int g = lane >> 2, c = lane & 3;
    const int rg = w >> 1;       // row group 0..7
    const int kh = w & 1;        // key half (S) == dim half (PV)

    const __half* Qg = g_Qh + (size_t)b * SEQ * DIM;
    const __half* Kg = g_Kh + (size_t)b * SEQ * DIM;
    const __half* Vg = g_Vth + (size_t)b * DIM * SEQ;

    const uint32_t ksm = (uint32_t)__cvta_generic_to_shared(Ksb);
    const uint32_t vsm = (uint32_t)__cvta_generic_to_shared(Vtb);
    const uint32_t psm = (uint32_t)__cvta_generic_to_shared(Ps);

    const uint32_t klane = (uint32_t)(((lane & 7) * KSTR + (lane >> 3) * 8) * 2);
    const uint32_t vlane = (uint32_t)(((lane & 7) * VSTR + (lane >> 3) * 8) * 2);
    const uint32_t palane = (uint32_t)(((rg * 16 + ((lane >> 3) & 1) * 8 + (lane & 7)) * PSTR
                                        + (lane >> 4) * 8) * 2);

    // Q fragments: 8 k-steps x 4 regs (perm16 gmem layout), rows rg*16..
    uint32_t qf[8][4];
    {
        size_t qr = (size_t)(q0 + rg * 16 + g) * DIM;
#pragma unroll
        for (int ks = 0; ks < 8; ks++) {
            uint2 t0 = *(const uint2*)(Qg + qr + ks * 16 + 4 * c);
            uint2 t1 = *(const uint2*)(Qg + qr + 8 * DIM + ks * 16 + 4 * c);
            qf[ks][0] = t0.x; qf[ks][2] = t0.y;
            qf[ks][1] = t1.x; qf[ks][3] = t1.y;
        }
    }

    float o[8][4];
#pragma unroll
    for (int nt = 0; nt < 8; nt++)
#pragma unroll
        for (int j = 0; j < 4; j++) o[nt][j] = 0.0f;
    float l0 = 0.0f, l1 = 0.0f;

    // prefetch tile 0: K 64x128 (1024 slots), V 128x64 (1024 slots)
#pragma unroll
    for (int i = 0; i < 2; i++) {
        int slot = tid + i * 512;
        int r = slot >> 4, cc = (slot & 15) * 8;
        cp16(Ksb + r * KSTR + cc, Kg + (size_t)r * DIM + cc);
    }
#pragma unroll
    for (int i = 0; i < 2; i++) {
        int slot = tid + i * 512;
        int r = slot >> 3, cc = (slot & 7) * 8;
        cp16(Vtb + r * VSTR + cc, Vg + (size_t)r * SEQ + cc);
    }
    cp_commit();

    for (int t = 0; t < NT64; t++) {
        cp_wait_all();
        __syncthreads();   // K/V ready; previous tile's P reads done
        if (t < NT64 - 1) {
            int k0 = (t + 1) * TK;
            int kso = ((t + 1) & 1) * KSTAGE;
            int vso = ((t + 1) & 1) * VSTAGE;
#pragma unroll
            for (int i = 0; i < 2; i++) {
                int slot = tid + i * 512;
                int r = slot >> 4, cc = (slot & 15) * 8;
                cp16(Ksb + kso + r * KSTR + cc, Kg + (size_t)(k0 + r) * DIM + cc);
            }
#pragma unroll
            for (int i = 0; i < 2; i++) {
                int slot = tid + i * 512;
                int r = slot >> 3, cc = (slot & 7) * 8;
                cp16(Vtb + vso + r * VSTR + cc, Vg + (size_t)r * SEQ + k0 + cc);
            }
            cp_commit();
        }

        // ---- S phase: rows rg*16.., keys kh*32 + nt*8 ----
        const uint32_t kbase = ksm + (uint32_t)((t & 1) * KSTAGE * 2)
                             + (uint32_t)(kh * 32 * KSTR * 2) + klane;
        float s[4][4];
#pragma unroll
        for (int nt = 0; nt < 4; nt++) {
            s[nt][0] = 0.0f; s[nt][1] = 0.0f; s[nt][2] = 0.0f; s[nt][3] = 0.0f;
        }
#pragma unroll
        for (int q = 0; q < 4; q++) {
#pragma unroll
            for (int nt = 0; nt < 4; nt++) {
                uint32_t b0, b1, b2, b3;
                LDSM4(b0, b1, b2, b3, kbase + (uint32_t)(nt * 8 * KSTR * 2) + q * 64);
                mma_f16(s[nt], qf[2 * q],     b0, b1);
                mma_f16(s[nt], qf[2 * q + 1], b2, b3);
            }
        }

        // ---- softmax: p = 2^(s-8), write P (fp16) to smem ----
#pragma unroll
        for (int nt = 0; nt < 4; nt++) {
            float e0 = fast_exp2(s[nt][0] - SHIFT);
            float e1 = fast_exp2(s[nt][1] - SHIFT);
            float e2 = fast_exp2(s[nt][2] - SHIFT);
            float e3 = fast_exp2(s[nt][3] - SHIFT);
            l0 += e0 + e1;
            l1 += e2 + e3;
            int col = kh * 32 + nt * 8 + 2 * c;
            *(uint32_t*)(Ps + (rg * 16 + g) * PSTR + col) = pack_h2(e0, e1);
            *(uint32_t*)(Ps + (rg * 16 + g + 8) * PSTR + col) = pack_h2(e2, e3);
        }
        __syncthreads();   // P complete for all warps

        // ---- PV phase: rows rg*16.., dims kh*64 + nt*8 ----
        const uint32_t vbase = vsm + (uint32_t)((t & 1) * VSTAGE * 2)
                             + (uint32_t)(kh * 64 * VSTR * 2) + vlane;
#pragma unroll
        for (int q2 = 0; q2 < 2; q2++) {
            uint32_t af0[4], af1[4];
            LDSM4(af0[0], af0[1], af0[2], af0[3], psm + palane + (uint32_t)(q2 * 64));
            LDSM4(af1[0], af1[1], af1[2], af1[3], psm + palane + (uint32_t)(q2 * 64 + 32));
#pragma unroll
            for (int nt = 0; nt < 8; nt++) {
                uint32_t b0, b1, b2, b3;
                LDSM4(b0, b1, b2, b3, vbase + (uint32_t)(nt * 8 * VSTR * 2) + q2 * 64);
                mma_f16(o[nt], af0, b0, b1);
                mma_f16(o[nt], af1, b2, b3);
            }
        }
    }

    // ---- l: reduce over c lanes, combine key halves via smem ----
    l0 += __shfl_xor_sync(0xffffffffu, l0, 1);
    l0 += __shfl_xor_sync(0xffffffffu, l0, 2);
    l1 += __shfl_xor_sync(0xffffffffu, l1, 1);
    l1 += __shfl_xor_sync(0xffffffffu, l1, 2);
    if (c == 0) {
        Lbuf[kh][rg * 16 + g] = l0;
        Lbuf[kh][rg * 16 + g + 8] = l1;
    }
    __syncthreads();
    float inv0 = 1.0f / (Lbuf[0][rg * 16 + g] + Lbuf[1][rg * 16 + g]);
    float inv1 = 1.0f / (Lbuf[0][rg * 16 + g + 8] + Lbuf[1][rg * 16 + g + 8]);

    size_t r0 = ((size_t)b * SEQ + q0 + rg * 16 + g) * DIM + kh * 64;
    size_t r1 = r0 + 8 * DIM;
#pragma unroll
    for (int nt = 0; nt < 8; nt++) {
        int col = nt * 8 + 2 * c;
        *(float2*)&out[r0 + col] = make_float2(o[nt][0] * inv0, o[nt][1] * inv0);
        *(float2*)&out[r1 + col] = make_float2(o[nt][2] * inv1, o[nt][3] * inv1);
    }
}

// ---------------------------------------------------------------------------
extern "C" void kernel_launch(void* const* d_in, const int* in_sizes, int n_in,
                              void* d_out, int out_size) {
    const float* x    = (const float*)d_in[0];
    const float* W    = (const float*)d_in[1];
    const float* bias = (const float*)d_in[2];
    float* out = (float*)d_out;

    conv_x_kernel<<<(MTOT * DMODEL / 4) / 256, 256>>>(x);
    conv_w_kernel<<<(NE * DMODEL) / 256, 256>>>(W);

    dim3 g1(128, 3);
    qkv_mma_kernel<<<g1, 256>>>(bias);

    cudaFuncSetAttribute(attn_kernel, cudaFuncAttributeMaxDynamicSharedMemorySize,
                         ATTN_SMEM);
    dim3 g2(SEQ / 128, BATCH);
    attn_kernel<<<g2, 512, ATTN_SMEM>>>(out);
}